// round 17
// baseline (speedup 1.0000x reference)
#include <cuda_runtime.h>
#include <cstddef>
#include <cstdint>

// FastNGramLM advance, round 17: plane-split.
//  - next plane: hypothesis-invariant template staged ONCE in smem (4KB),
//    shipped 8x by TMA immediately after the chain; completion wait is
//    overlapped by the entire score-plane phase.
//  - score plane: written DIRECTLY from registers via STG.128 (no staging,
//    no smem double-pass): sc = acc_j + wf, one float4 per thread per row.
//  - patches: score patches = barrier-ordered STG rounds (deep->shallow);
//    next patches after tid0's wait_group 0 (TMA writes landed) + barrier.
//  - smem 4KB -> full occupancy; ~8 barriers per block total.
//
// Output: d_out[0..B*V) = scores f32, d_out[B*V..2BV) = next as exact f32.

#define VMAX  1024
#define DEPTH 3
#define ARCS  16
#define HPB   8
#define TPB   256

__device__ __forceinline__ uint32_t smem_u32(const void* p) {
    return (uint32_t)__cvta_generic_to_shared(p);
}

__global__ __launch_bounds__(TPB, 8)
void ngram_fused_kernel(const float* __restrict__ arcs_weights,
                        const float* __restrict__ backoff_weights,
                        const int*   __restrict__ ilabels,
                        const int*   __restrict__ to_states,
                        const int*   __restrict__ backoff_to,
                        const int*   __restrict__ state_start,
                        const int*   __restrict__ state_end,
                        const int*   __restrict__ states,
                        float*       __restrict__ out_scores,
                        float*       __restrict__ out_next,
                        int B, int V)
{
    __shared__ __align__(128) float s_nx[VMAX];   // next-plane template (4KB)
    __shared__ float s_acc[HPB];

    const int tid = threadIdx.x;
    const int h0  = blockIdx.x * HPB;

    // ---- dense fallback weights -> registers; next template -> smem ----
    const float4 wf = __ldg((const float4*)arcs_weights + tid);
    {
        const int4 nfi = __ldg((const int4*)to_states + tid);
        float4 nfv;
        nfv.x = (float)nfi.x; nfv.y = (float)nfi.y;
        nfv.z = (float)nfi.z; nfv.w = (float)nfi.w;
        *(float4*)&s_nx[tid * 4] = nfv;
    }

    // ---- chain phase: threads 0..127 = 8 hyps x 16 lanes, regs-resident ----
    int   lab[DEPTH];
    float scr[DEPTH];
    float nxf[DEPTH];
    const int jh = tid >> 4;
    if (tid < HPB * ARCS) {
        const int lane = tid & 15;
        const int h    = h0 + jh;
        int   cur = (h < B) ? __ldg(&states[h]) : 0;
        float acc = 0.0f;
        #pragma unroll
        for (int d = 0; d < DEPTH; ++d) {
            lab[d] = -1; scr[d] = 0.0f; nxf[d] = 0.0f;
            if (cur != 0) {                    // START == 0
                const int st  = __ldg(&state_start[cur]);
                const int en  = __ldg(&state_end[cur]);
                const int idx = st + lane;
                if (idx < en) {
                    lab[d] = __ldg(&ilabels[idx]);
                    scr[d] = acc + __ldg(&arcs_weights[idx]);
                    nxf[d] = (float)__ldg(&to_states[idx]);
                }
                acc += __ldg(&backoff_weights[cur]);
                cur  = __ldg(&backoff_to[cur]);
            }
        }
        if (lane == 0) s_acc[jh] = acc;
    }
    __syncthreads();   // template + s_acc ready                        [A]

    // ---- ship next plane: 8 bulk copies of the SAME 4KB template ----
    if (tid == 0) {
        asm volatile("fence.proxy.async.shared::cta;" ::: "memory");
        const uint32_t snx = smem_u32(s_nx);
        #pragma unroll
        for (int j = 0; j < HPB; ++j) {
            const int h = h0 + j;
            if (h >= B) break;
            asm volatile(
                "cp.async.bulk.global.shared::cta.bulk_group [%0], [%1], %2;"
                :: "l"(out_next + (size_t)h * V), "r"(snx), "r"(V * 4)
                : "memory");
        }
        asm volatile("cp.async.bulk.commit_group;" ::: "memory");
        // no wait here: completion overlapped by all score-plane work
    }

    // ---- score plane: direct STG.128 from registers, 8 rows ----
    const int lab0 = tid * 4;
    #pragma unroll
    for (int j = 0; j < HPB; ++j) {
        const int h = h0 + j;
        if (h >= B) break;
        const float acc = s_acc[j];
        float4 sc;
        sc.x = acc + wf.x; sc.y = acc + wf.y;
        sc.z = acc + wf.z; sc.w = acc + wf.w;
        *(float4*)&out_scores[(size_t)h * V + lab0] = sc;
    }
    __syncthreads();   // dense scores written                          [B]

    // ---- score patches: deepest -> shallowest, barrier-ordered ----
    const size_t hbase = (size_t)(h0 + jh) * (size_t)V;
    const bool   owner = (tid < HPB * ARCS) && (h0 + jh < B);
    #pragma unroll
    for (int d = DEPTH - 1; d >= 0; --d) {
        if (owner && lab[d] >= 0)
            out_scores[hbase + lab[d]] = scr[d];
        __syncthreads();   // order rounds; last one also precedes wait [C,D,E]
    }

    // ---- next patches: after TMA writes are complete ----
    if (tid == 0)
        asm volatile("cp.async.bulk.wait_group 0;" ::: "memory");
    __syncthreads();   // completion published to all warps             [F]

    #pragma unroll
    for (int d = DEPTH - 1; d >= 0; --d) {
        if (owner && lab[d] >= 0)
            out_next[hbase + lab[d]] = nxf[d];
        if (d > 0) __syncthreads();                                  // [G,H]
    }
}

extern "C" void kernel_launch(void* const* d_in, const int* in_sizes, int n_in,
                              void* d_out, int out_size)
{
    // Classify inputs by element count (robust to metadata ordering):
    //   arcs group (3x largest):  arcs_weights, ilabels, to_states
    //   state group (4x middle):  backoff_weights, backoff_to, start, end
    //   states: the remaining batch-sized array
    long long max_sz = 0;
    for (int i = 0; i < n_in; ++i)
        if ((long long)in_sizes[i] > max_sz) max_sz = in_sizes[i];

    long long arc_sz = max_sz;
    long long n_sz = -1;
    for (int i = 0; i < n_in; ++i) {
        int cnt = 0;
        for (int j = 0; j < n_in; ++j)
            if (in_sizes[j] == in_sizes[i]) ++cnt;
        if (cnt == 4) { n_sz = in_sizes[i]; break; }
    }

    const void* arc_grp[3];  int na = 0;
    const void* st_grp[4];   int ns = 0;
    const void* states_ptr = nullptr;
    long long B = 0;
    for (int i = 0; i < n_in; ++i) {
        if (in_sizes[i] == arc_sz && na < 3)      arc_grp[na++] = d_in[i];
        else if (in_sizes[i] == n_sz && ns < 4)   st_grp[ns++]  = d_in[i];
        else { states_ptr = d_in[i]; B = in_sizes[i]; }
    }

    const float* arcs_weights    = (const float*)arc_grp[0];
    const int*   ilabels         = (const int*)  arc_grp[1];
    const int*   to_states       = (const int*)  arc_grp[2];
    const float* backoff_weights = (const float*)st_grp[0];
    const int*   backoff_to      = (const int*)  st_grp[1];
    const int*   state_start     = (const int*)  st_grp[2];
    const int*   state_end       = (const int*)  st_grp[3];
    const int*   states          = (const int*)  states_ptr;

    const long long V = (long long)out_size / (2 * B);
    float* out_scores = (float*)d_out;
    float* out_next   = (float*)d_out + (size_t)B * (size_t)V;

    const int grid = (int)((B + HPB - 1) / HPB);
    ngram_fused_kernel<<<grid, TPB>>>(
        arcs_weights, backoff_weights, ilabels, to_states,
        backoff_to, state_start, state_end, states,
        out_scores, out_next, (int)B, (int)V);
}